// round 8
// baseline (speedup 1.0000x reference)
#include <cuda_runtime.h>
#include <cuda_bf16.h>
#include <math.h>
#include <stdint.h>

#define TT 4096
#define DD 2048
#define FFDIM 8192
#define EE 8
#define MTILES 16   // covers up to 2048 tokens/expert (mean 512)

// ---------------- device scratch ----------------
__device__ float g_H[(size_t)TT * FFDIM];
__device__ int   g_idx[TT];
__device__ float g_w[TT];
__device__ int   g_counts[EE];
__device__ int   g_offsets[EE];
__device__ int   g_rank[TT];
__device__ int   g_perm[TT];

// ---------------- helpers ----------------
__device__ __forceinline__ uint32_t smem_u32(const void* p) {
    uint32_t a;
    asm("{ .reg .u64 t; cvta.to.shared.u64 t, %1; cvt.u32.u64 %0, t; }" : "=r"(a) : "l"(p));
    return a;
}
__device__ __forceinline__ uint32_t sw128(uint32_t b) { return b ^ ((b >> 3) & 0x70); }

// split fp32 pair -> bf16x2 hi + bf16x2 lo (f0 in low half, f1 in high half)
__device__ __forceinline__ void split2(float f0, float f1, uint32_t& hi, uint32_t& lo) {
    uint32_t h;
    asm("cvt.rn.bf16x2.f32 %0, %1, %2;" : "=r"(h) : "f"(f1), "f"(f0));
    float h0 = __uint_as_float(h << 16);
    float h1 = __uint_as_float(h & 0xFFFF0000u);
    float l0 = f0 - h0, l1 = f1 - h1;
    uint32_t l;
    asm("cvt.rn.bf16x2.f32 %0, %1, %2;" : "=r"(l) : "f"(l1), "f"(l0));
    hi = h; lo = l;
}

__device__ __forceinline__ void ldm4(uint32_t* r, uint32_t addr) {
    asm volatile("ldmatrix.sync.aligned.m8n8.x4.shared.b16 {%0,%1,%2,%3}, [%4];"
        : "=r"(r[0]), "=r"(r[1]), "=r"(r[2]), "=r"(r[3]) : "r"(addr));
}

__device__ __forceinline__ void mma_bf16(float* d, const uint32_t* a, uint32_t b0, uint32_t b1) {
    asm volatile("mma.sync.aligned.m16n8k16.row.col.f32.bf16.bf16.f32 "
        "{%0,%1,%2,%3}, {%4,%5,%6,%7}, {%8,%9}, {%0,%1,%2,%3};"
        : "+f"(d[0]), "+f"(d[1]), "+f"(d[2]), "+f"(d[3])
        : "r"(a[0]), "r"(a[1]), "r"(a[2]), "r"(a[3]), "r"(b0), "r"(b1));
}

__device__ __forceinline__ float gelu_exact(float v) {
    return 0.5f * v * (1.0f + erff(v * 0.70710678118654752440f));
}

// ---------------- router pipeline ----------------
__global__ void zero_counts_kernel() { if (threadIdx.x < EE) g_counts[threadIdx.x] = 0; }

__global__ void router_kernel(const float* __restrict__ x, const float* __restrict__ Wr) {
    const int t = blockIdx.x;
    const int warp = threadIdx.x >> 5, lane = threadIdx.x & 31;
    const float* xr = x + (size_t)t * DD;
    const float* wr = Wr + (size_t)warp * DD;
    float acc = 0.0f;
    for (int d = lane * 4; d < DD; d += 128) {
        float4 xv = *(const float4*)(xr + d);
        float4 wv = *(const float4*)(wr + d);
        acc += xv.x * wv.x + xv.y * wv.y + xv.z * wv.z + xv.w * wv.w;
    }
    #pragma unroll
    for (int o = 16; o; o >>= 1) acc += __shfl_xor_sync(0xFFFFFFFFu, acc, o);
    __shared__ float slog[EE];
    if (lane == 0) slog[warp] = acc;
    __syncthreads();
    if (threadIdx.x == 0) {
        float mx = slog[0]; int mi = 0;
        #pragma unroll
        for (int e = 1; e < EE; e++) if (slog[e] > mx) { mx = slog[e]; mi = e; }
        float s = 0.0f;
        #pragma unroll
        for (int e = 0; e < EE; e++) s += expf(slog[e] - mx);
        g_idx[t] = mi;
        g_w[t] = 1.0f / s;
        g_rank[t] = atomicAdd(&g_counts[mi], 1);
    }
}

__global__ void scan_kernel() {
    int s = 0;
    #pragma unroll
    for (int e = 0; e < EE; e++) { g_offsets[e] = s; s += g_counts[e]; }
}

__global__ void scatter_kernel() {
    int t = blockIdx.x * blockDim.x + threadIdx.x;
    if (t < TT) g_perm[g_offsets[g_idx[t]] + g_rank[t]] = t;
}

// ---------------- mma.sync grouped GEMM (split-bf16 3-pass) ----------------
// MODE 0: H[srow,:] = gelu( x[perm,:] @ W1[e] )     K=DD,   N=FFDIM
// MODE 1: out[tok,:] = ( H[srow,:] @ W2[e] ) * w     K=FFDIM, N=DD
constexpr int BM = 128, BN = 128, BKS = 64;
constexpr int TILE_BYTES = BM * BKS * 2;         // 16 KB per bf16 tile
constexpr int BUF_BYTES  = 4 * TILE_BYTES;       // Ahi, Alo, Bhi, Blo
constexpr int SMEM_TOTAL = 2 * BUF_BYTES;        // 128 KB double-buffered

template<int MODE>
__global__ __launch_bounds__(256, 1) void moe_gemm_mma(
    const float* __restrict__ Ag, const float* __restrict__ Bg, float* __restrict__ Cg)
{
    constexpr int K  = (MODE == 0) ? DD : FFDIM;
    constexpr int NN = (MODE == 0) ? FFDIM : DD;
    constexpr int KT = K / BKS;

    const int e   = blockIdx.z;
    const int cnt = g_counts[e];
    const int m0  = blockIdx.x * BM;             // m fastest -> B tile L2 reuse
    if (m0 >= cnt) return;
    const int off = g_offsets[e];
    const int n0  = blockIdx.y * BN;

    extern __shared__ __align__(1024) char smem[];
    const uint32_t su = smem_u32(smem);
    const int tid = threadIdx.x, wid = tid >> 5, lane = tid & 31;

    // ---- staging geometry ----
    // A: thread owns 8 (m, k4) units: m = (tid>>4) + 16*i, k4 = tid&15
    const float* aRow[8];
    uint32_t sAoff[8];
    {
        const int mB = tid >> 4, k4 = tid & 15;
        #pragma unroll
        for (int i = 0; i < 8; i++) {
            int m = mB + 16 * i;
            int r = m0 + m;
            bool v = r < cnt;
            const float* base;
            if (MODE == 0) {
                int tok = v ? g_perm[off + r] : g_perm[off];
                base = Ag + (size_t)tok * DD;
            } else {
                base = g_H + (size_t)(off + (v ? r : 0)) * FFDIM;
            }
            aRow[i]  = base + k4 * 4;
            sAoff[i] = sw128((uint32_t)(m * 128 + k4 * 8));
        }
    }
    // B: thread owns n-row rB = tid&127, 8 k-groups with stagger (conflict break)
    const int rB = tid & 127;
    const float* bCol = Bg + (size_t)e * ((size_t)K * NN) + (size_t)(n0 + rB);
    int kkB[8]; uint32_t sBoff[8];
    {
        const int gB = tid >> 7, stag = (rB >> 3) & 3;
        #pragma unroll
        for (int i = 0; i < 8; i++) {
            int g = ((gB + 2 * i) + stag) & 15;
            kkB[i]   = g * 4;
            sBoff[i] = sw128((uint32_t)(rB * 128 + g * 8));
        }
    }

    // ---- ldmatrix geometry: warp (wm, wn) owns 32(m) x 64(n) ----
    const int wm = wid & 3, wn = wid >> 2;
    uint32_t aB[2], bB[4];
    #pragma unroll
    for (int c = 0; c < 2; c++) {
        int row = wm * 32 + c * 16 + (lane & 15);
        aB[c] = (uint32_t)(row * 128 + (lane >> 4) * 16);
    }
    #pragma unroll
    for (int j = 0; j < 4; j++) {
        int row = wn * 64 + j * 16 + (lane & 15);
        bB[j] = (uint32_t)(row * 128 + (lane >> 4) * 16);
    }

    float acc[2][8][4];
    #pragma unroll
    for (int c = 0; c < 2; c++)
        #pragma unroll
        for (int j = 0; j < 8; j++)
            #pragma unroll
            for (int q = 0; q < 4; q++) acc[c][j][q] = 0.0f;

    float4 pa[8], pb[8];

    auto preload = [&](int kt) {
        const int k0 = kt * BKS;
        #pragma unroll
        for (int i = 0; i < 8; i++) pa[i] = *(const float4*)(aRow[i] + k0);
        #pragma unroll
        for (int i = 0; i < 8; i++) {
            const float* p = bCol + (size_t)(k0 + kkB[i]) * NN;
            pb[i] = make_float4(p[0], p[(size_t)NN], p[(size_t)2 * NN], p[(size_t)3 * NN]);
        }
    };

    auto store_stage = [&](int b) {
        char* Ahi = smem + b * BUF_BYTES;
        char* Alo = Ahi + TILE_BYTES;
        char* Bhi = Alo + TILE_BYTES;
        char* Blo = Bhi + TILE_BYTES;
        #pragma unroll
        for (int i = 0; i < 8; i++) {
            uint32_t h0, l0, h1, l1;
            split2(pa[i].x, pa[i].y, h0, l0);
            split2(pa[i].z, pa[i].w, h1, l1);
            *(uint2*)(Ahi + sAoff[i]) = make_uint2(h0, h1);
            *(uint2*)(Alo + sAoff[i]) = make_uint2(l0, l1);
        }
        #pragma unroll
        for (int i = 0; i < 8; i++) {
            uint32_t h0, l0, h1, l1;
            split2(pb[i].x, pb[i].y, h0, l0);
            split2(pb[i].z, pb[i].w, h1, l1);
            *(uint2*)(Bhi + sBoff[i]) = make_uint2(h0, h1);
            *(uint2*)(Blo + sBoff[i]) = make_uint2(l0, l1);
        }
    };

    preload(0);
    store_stage(0);
    __syncthreads();

    for (int kt = 0; kt < KT; kt++) {
        const int buf = kt & 1;
        const bool more = (kt + 1 < KT);
        if (more) preload(kt + 1);          // LDGs overlap the MMA section

        const uint32_t baseA  = su + buf * BUF_BYTES;
        const uint32_t baseAl = baseA + TILE_BYTES;
        const uint32_t baseB  = baseA + 2 * TILE_BYTES;
        const uint32_t baseBl = baseA + 3 * TILE_BYTES;

        #pragma unroll
        for (int ks = 0; ks < 4; ks++) {
            uint32_t ah[2][4], al[2][4], bh[4][4], bl[4][4];
            #pragma unroll
            for (int c = 0; c < 2; c++) {
                uint32_t o = sw128(aB[c] + ks * 32);
                ldm4(ah[c], baseA  + o);
                ldm4(al[c], baseAl + o);
            }
            #pragma unroll
            for (int j = 0; j < 4; j++) {
                uint32_t o = sw128(bB[j] + ks * 32);
                ldm4(bh[j], baseB  + o);
                ldm4(bl[j], baseBl + o);
            }
            // ---- pass 1: hi * hi (16 independent MMAs) ----
            #pragma unroll
            for (int j = 0; j < 4; j++)
                #pragma unroll
                for (int c = 0; c < 2; c++) {
                    mma_bf16(acc[c][2 * j],     ah[c], bh[j][0], bh[j][2]);
                    mma_bf16(acc[c][2 * j + 1], ah[c], bh[j][1], bh[j][3]);
                }
            // ---- pass 2: hi * lo ----
            #pragma unroll
            for (int j = 0; j < 4; j++)
                #pragma unroll
                for (int c = 0; c < 2; c++) {
                    mma_bf16(acc[c][2 * j],     ah[c], bl[j][0], bl[j][2]);
                    mma_bf16(acc[c][2 * j + 1], ah[c], bl[j][1], bl[j][3]);
                }
            // ---- pass 3: lo * hi ----
            #pragma unroll
            for (int j = 0; j < 4; j++)
                #pragma unroll
                for (int c = 0; c < 2; c++) {
                    mma_bf16(acc[c][2 * j],     al[c], bh[j][0], bh[j][2]);
                    mma_bf16(acc[c][2 * j + 1], al[c], bh[j][1], bh[j][3]);
                }
        }
        if (more) store_stage(buf ^ 1);
        __syncthreads();
    }

    // ---------------- epilogue (register accumulators -> gmem) ----------------
    const int mw = m0 + wm * 32;
    const int nw = n0 + wn * 64;
    #pragma unroll
    for (int c = 0; c < 2; c++) {
        #pragma unroll
        for (int half = 0; half < 2; half++) {
            const int r = mw + c * 16 + (lane >> 2) + half * 8;
            if (r >= cnt) continue;
            float s = 0.0f; float* cp;
            if (MODE == 0) {
                cp = g_H + (size_t)(off + r) * FFDIM + nw;
            } else {
                const int tok = g_perm[off + r];
                s = g_w[tok];
                cp = Cg + (size_t)tok * DD + nw;
            }
            #pragma unroll
            for (int j = 0; j < 8; j++) {
                float v0 = acc[c][j][half * 2];
                float v1 = acc[c][j][half * 2 + 1];
                if (MODE == 0) { v0 = gelu_exact(v0); v1 = gelu_exact(v1); }
                else           { v0 *= s; v1 *= s; }
                *(float2*)(cp + j * 8 + (lane & 3) * 2) = make_float2(v0, v1);
            }
        }
    }
}

// ---------------- launch ----------------
extern "C" void kernel_launch(void* const* d_in, const int* in_sizes, int n_in,
                              void* d_out, int out_size) {
    const float* x  = (const float*)d_in[0];
    const float* Wr = (const float*)d_in[1];
    const float* W1 = (const float*)d_in[2];
    const float* W2 = (const float*)d_in[3];
    float* out = (float*)d_out;

    cudaFuncSetAttribute(moe_gemm_mma<0>, cudaFuncAttributeMaxDynamicSharedMemorySize, SMEM_TOTAL);
    cudaFuncSetAttribute(moe_gemm_mma<1>, cudaFuncAttributeMaxDynamicSharedMemorySize, SMEM_TOTAL);

    zero_counts_kernel<<<1, 32>>>();
    router_kernel<<<TT, 256>>>(x, Wr);
    scan_kernel<<<1, 1>>>();
    scatter_kernel<<<TT / 256, 256>>>();

    dim3 g1(MTILES, FFDIM / BN, EE);
    moe_gemm_mma<0><<<g1, 256, SMEM_TOTAL>>>(x, W1, nullptr);

    dim3 g2(MTILES, DD / BN, EE);
    moe_gemm_mma<1><<<g2, 256, SMEM_TOTAL>>>(nullptr, W2, out);
}

// round 9
// speedup vs baseline: 1.0476x; 1.0476x over previous
#include <cuda_runtime.h>
#include <cuda_bf16.h>
#include <math.h>
#include <stdint.h>

#define TT 4096
#define DD 2048
#define FFDIM 8192
#define EE 8
#define MTILES 16   // covers up to 2048 tokens/expert (mean 512)

// ---------------- device scratch ----------------
__device__ float g_H[(size_t)TT * FFDIM];
__device__ int   g_idx[TT];
__device__ float g_w[TT];
__device__ int   g_counts[EE];
__device__ int   g_offsets[EE];
__device__ int   g_rank[TT];
__device__ int   g_perm[TT];

// ---------------- helpers ----------------
__device__ __forceinline__ uint32_t smem_u32(const void* p) {
    uint32_t a;
    asm("{ .reg .u64 t; cvta.to.shared.u64 t, %1; cvt.u32.u64 %0, t; }" : "=r"(a) : "l"(p));
    return a;
}
__device__ __forceinline__ uint32_t sw128(uint32_t b) { return b ^ ((b >> 3) & 0x70); }

// split fp32 pair -> bf16x2 hi + bf16x2 lo (f0 low half, f1 high half)
__device__ __forceinline__ void split2(float f0, float f1, uint32_t& hi, uint32_t& lo) {
    uint32_t h;
    asm("cvt.rn.bf16x2.f32 %0, %1, %2;" : "=r"(h) : "f"(f1), "f"(f0));
    float h0 = __uint_as_float(h << 16);
    float h1 = __uint_as_float(h & 0xFFFF0000u);
    float l0 = f0 - h0, l1 = f1 - h1;
    uint32_t l;
    asm("cvt.rn.bf16x2.f32 %0, %1, %2;" : "=r"(l) : "f"(l1), "f"(l0));
    hi = h; lo = l;
}

__device__ __forceinline__ void ldm4(uint32_t* r, uint32_t addr) {
    asm volatile("ldmatrix.sync.aligned.m8n8.x4.shared.b16 {%0,%1,%2,%3}, [%4];"
        : "=r"(r[0]), "=r"(r[1]), "=r"(r[2]), "=r"(r[3]) : "r"(addr));
}

__device__ __forceinline__ void mma_bf16(float* d, const uint32_t* a, uint32_t b0, uint32_t b1) {
    asm volatile("mma.sync.aligned.m16n8k16.row.col.f32.bf16.bf16.f32 "
        "{%0,%1,%2,%3}, {%4,%5,%6,%7}, {%8,%9}, {%0,%1,%2,%3};"
        : "+f"(d[0]), "+f"(d[1]), "+f"(d[2]), "+f"(d[3])
        : "r"(a[0]), "r"(a[1]), "r"(a[2]), "r"(a[3]), "r"(b0), "r"(b1));
}

__device__ __forceinline__ float gelu_exact(float v) {
    return 0.5f * v * (1.0f + erff(v * 0.70710678118654752440f));
}

// ---------------- router pipeline ----------------
__global__ void zero_counts_kernel() { if (threadIdx.x < EE) g_counts[threadIdx.x] = 0; }

__global__ void router_kernel(const float* __restrict__ x, const float* __restrict__ Wr) {
    const int t = blockIdx.x;
    const int warp = threadIdx.x >> 5, lane = threadIdx.x & 31;
    const float* xr = x + (size_t)t * DD;
    const float* wr = Wr + (size_t)warp * DD;
    float acc = 0.0f;
    for (int d = lane * 4; d < DD; d += 128) {
        float4 xv = *(const float4*)(xr + d);
        float4 wv = *(const float4*)(wr + d);
        acc += xv.x * wv.x + xv.y * wv.y + xv.z * wv.z + xv.w * wv.w;
    }
    #pragma unroll
    for (int o = 16; o; o >>= 1) acc += __shfl_xor_sync(0xFFFFFFFFu, acc, o);
    __shared__ float slog[EE];
    if (lane == 0) slog[warp] = acc;
    __syncthreads();
    if (threadIdx.x == 0) {
        float mx = slog[0]; int mi = 0;
        #pragma unroll
        for (int e = 1; e < EE; e++) if (slog[e] > mx) { mx = slog[e]; mi = e; }
        float s = 0.0f;
        #pragma unroll
        for (int e = 0; e < EE; e++) s += expf(slog[e] - mx);
        g_idx[t] = mi;
        g_w[t] = 1.0f / s;
        g_rank[t] = atomicAdd(&g_counts[mi], 1);
    }
}

__global__ void scan_kernel() {
    int s = 0;
    #pragma unroll
    for (int e = 0; e < EE; e++) { g_offsets[e] = s; s += g_counts[e]; }
}

__global__ void scatter_kernel() {
    int t = blockIdx.x * blockDim.x + threadIdx.x;
    if (t < TT) g_perm[g_offsets[g_idx[t]] + g_rank[t]] = t;
}

// ---------------- mma.sync grouped GEMM (split-bf16 3-pass) ----------------
// 128 threads/CTA, tile 128m x 64n x 64k, 2 CTAs/SM for barrier-desynced overlap.
// MODE 0: H[srow,:] = gelu( x[perm,:] @ W1[e] )     K=DD,   N=FFDIM
// MODE 1: out[tok,:] = ( H[srow,:] @ W2[e] ) * w     K=FFDIM, N=DD
constexpr int BM = 128, BN = 64, BKS = 64;
constexpr int A_TILE = BM * BKS * 2;             // 16 KB
constexpr int B_TILE = BN * BKS * 2;             // 8 KB
constexpr int BUF_BYTES = 2 * A_TILE + 2 * B_TILE;  // Ahi,Alo,Bhi,Blo = 48 KB
constexpr int SMEM_TOTAL = 2 * BUF_BYTES;        // 96 KB double-buffered

template<int MODE>
__global__ __launch_bounds__(128, 2) void moe_gemm_mma(
    const float* __restrict__ Ag, const float* __restrict__ Bg, float* __restrict__ Cg)
{
    constexpr int K  = (MODE == 0) ? DD : FFDIM;
    constexpr int NN = (MODE == 0) ? FFDIM : DD;
    constexpr int KT = K / BKS;

    const int e   = blockIdx.z;
    const int cnt = g_counts[e];
    const int m0  = blockIdx.x * BM;             // m fastest -> B tile L2 reuse
    if (m0 >= cnt) return;
    const int off = g_offsets[e];
    const int n0  = blockIdx.y * BN;

    extern __shared__ __align__(1024) char smem[];
    const uint32_t su = smem_u32(smem);
    const int tid = threadIdx.x, wid = tid >> 5, lane = tid & 31;

    // ---- staging geometry ----
    // A: thread owns 16 (m, k4) units: m = (tid>>4) + 8*i, k4 = tid&15
    const char* aBase = (MODE == 0) ? (const char*)Ag : (const char*)g_H;
    uint32_t aOff[16], sAoff[16];
    {
        const int mB = tid >> 4, k4 = tid & 15;
        #pragma unroll
        for (int i = 0; i < 16; i++) {
            int m = mB + 8 * i;
            int r = m0 + m;
            bool v = r < cnt;
            uint32_t rowBytes;
            if (MODE == 0) {
                int tok = v ? g_perm[off + r] : g_perm[off];
                rowBytes = (uint32_t)tok * (DD * 4u);
            } else {
                rowBytes = (uint32_t)(off + (v ? r : 0)) * (FFDIM * 4u);
            }
            aOff[i]  = rowBytes + k4 * 16u;
            sAoff[i] = sw128((uint32_t)(m * 128 + k4 * 8));
        }
    }
    // B: thread owns n-row rB = tid&63, 8 k-groups with stagger
    const int rB = tid & 63;
    const float* bCol = Bg + (size_t)e * ((size_t)K * NN) + (size_t)(n0 + rB);
    int kkB[8]; uint32_t sBoff[8];
    {
        const int gB = tid >> 6, stag = (rB >> 3) & 3;
        #pragma unroll
        for (int i = 0; i < 8; i++) {
            int g = ((gB + 2 * i) + stag) & 15;
            kkB[i]   = g * 4;
            sBoff[i] = sw128((uint32_t)(rB * 128 + g * 8));
        }
    }

    // ---- ldmatrix geometry: 4 warps, warp wid owns rows [wid*32, wid*32+32), all 64 n ----
    uint32_t aB[2], bB[4];
    #pragma unroll
    for (int c = 0; c < 2; c++) {
        int row = wid * 32 + c * 16 + (lane & 15);
        aB[c] = (uint32_t)(row * 128 + (lane >> 4) * 16);
    }
    #pragma unroll
    for (int j = 0; j < 4; j++) {
        int row = j * 16 + (lane & 15);
        bB[j] = (uint32_t)(row * 128 + (lane >> 4) * 16);
    }

    float acc[2][8][4];
    #pragma unroll
    for (int c = 0; c < 2; c++)
        #pragma unroll
        for (int j = 0; j < 8; j++)
            #pragma unroll
            for (int q = 0; q < 4; q++) acc[c][j][q] = 0.0f;

    float4 pb[8];
    auto preloadB = [&](int kt) {
        const int k0 = kt * BKS;
        #pragma unroll
        for (int i = 0; i < 8; i++) {
            const float* p = bCol + (size_t)(k0 + kkB[i]) * NN;
            pb[i] = make_float4(p[0], p[(size_t)NN], p[(size_t)2 * NN], p[(size_t)3 * NN]);
        }
    };

    auto stageA = [&](int kt, int b) {
        char* Ahi = smem + b * BUF_BYTES;
        char* Alo = Ahi + A_TILE;
        const uint32_t kByte = (uint32_t)(kt * BKS * 4);
        #pragma unroll
        for (int i = 0; i < 16; i++) {
            float4 v = *(const float4*)(aBase + aOff[i] + kByte);
            uint32_t h0, l0, h1, l1;
            split2(v.x, v.y, h0, l0);
            split2(v.z, v.w, h1, l1);
            *(uint2*)(Ahi + sAoff[i]) = make_uint2(h0, h1);
            *(uint2*)(Alo + sAoff[i]) = make_uint2(l0, l1);
        }
    };
    auto storeB = [&](int b) {
        char* Bhi = smem + b * BUF_BYTES + 2 * A_TILE;
        char* Blo = Bhi + B_TILE;
        #pragma unroll
        for (int i = 0; i < 8; i++) {
            uint32_t h0, l0, h1, l1;
            split2(pb[i].x, pb[i].y, h0, l0);
            split2(pb[i].z, pb[i].w, h1, l1);
            *(uint2*)(Bhi + sBoff[i]) = make_uint2(h0, h1);
            *(uint2*)(Blo + sBoff[i]) = make_uint2(l0, l1);
        }
    };

    preloadB(0);
    stageA(0, 0);
    storeB(0);
    __syncthreads();

    for (int kt = 0; kt < KT; kt++) {
        const int buf = kt & 1;
        const bool more = (kt + 1 < KT);
        if (more) preloadB(kt + 1);       // B LDGs overlap the MMA section

        const uint32_t baseA  = su + buf * BUF_BYTES;
        const uint32_t baseAl = baseA + A_TILE;
        const uint32_t baseB  = baseA + 2 * A_TILE;
        const uint32_t baseBl = baseB + B_TILE;

        #pragma unroll
        for (int ks = 0; ks < 4; ks++) {
            uint32_t ah[2][4], al[2][4], bh[4][4], bl[4][4];
            #pragma unroll
            for (int c = 0; c < 2; c++) {
                uint32_t o = sw128(aB[c] + ks * 32);
                ldm4(ah[c], baseA  + o);
                ldm4(al[c], baseAl + o);
            }
            #pragma unroll
            for (int j = 0; j < 4; j++) {
                uint32_t o = sw128(bB[j] + ks * 32);
                ldm4(bh[j], baseB  + o);
                ldm4(bl[j], baseBl + o);
            }
            #pragma unroll
            for (int j = 0; j < 4; j++)
                #pragma unroll
                for (int c = 0; c < 2; c++) {
                    mma_bf16(acc[c][2 * j],     ah[c], bh[j][0], bh[j][2]);
                    mma_bf16(acc[c][2 * j + 1], ah[c], bh[j][1], bh[j][3]);
                }
            #pragma unroll
            for (int j = 0; j < 4; j++)
                #pragma unroll
                for (int c = 0; c < 2; c++) {
                    mma_bf16(acc[c][2 * j],     ah[c], bl[j][0], bl[j][2]);
                    mma_bf16(acc[c][2 * j + 1], ah[c], bl[j][1], bl[j][3]);
                }
            #pragma unroll
            for (int j = 0; j < 4; j++)
                #pragma unroll
                for (int c = 0; c < 2; c++) {
                    mma_bf16(acc[c][2 * j],     al[c], bh[j][0], bh[j][2]);
                    mma_bf16(acc[c][2 * j + 1], al[c], bh[j][1], bh[j][3]);
                }
        }
        if (more) {
            stageA(kt + 1, buf ^ 1);
            storeB(buf ^ 1);
        }
        __syncthreads();
    }

    // ---------------- epilogue ----------------
    const int mw = m0 + wid * 32;
    #pragma unroll
    for (int c = 0; c < 2; c++) {
        #pragma unroll
        for (int half = 0; half < 2; half++) {
            const int r = mw + c * 16 + (lane >> 2) + half * 8;
            if (r >= cnt) continue;
            float s = 0.0f; float* cp;
            if (MODE == 0) {
                cp = g_H + (size_t)(off + r) * FFDIM + n0;
            } else {
                const int tok = g_perm[off + r];
                s = g_w[tok];
                cp = Cg + (size_t)tok * DD + n0;
            }
            #pragma unroll
            for (int j = 0; j < 8; j++) {
                float v0 = acc[c][j][half * 2];
                float v1 = acc[c][j][half * 2 + 1];
                if (MODE == 0) { v0 = gelu_exact(v0); v1 = gelu_exact(v1); }
                else           { v0 *= s; v1 *= s; }
                *(float2*)(cp + j * 8 + (lane & 3) * 2) = make_float2(v0, v1);
            }
        }
    }
}

// ---------------- launch ----------------
extern "C" void kernel_launch(void* const* d_in, const int* in_sizes, int n_in,
                              void* d_out, int out_size) {
    const float* x  = (const float*)d_in[0];
    const float* Wr = (const float*)d_in[1];
    const float* W1 = (const float*)d_in[2];
    const float* W2 = (const float*)d_in[3];
    float* out = (float*)d_out;

    cudaFuncSetAttribute(moe_gemm_mma<0>, cudaFuncAttributeMaxDynamicSharedMemorySize, SMEM_TOTAL);
    cudaFuncSetAttribute(moe_gemm_mma<1>, cudaFuncAttributeMaxDynamicSharedMemorySize, SMEM_TOTAL);

    zero_counts_kernel<<<1, 32>>>();
    router_kernel<<<TT, 256>>>(x, Wr);
    scan_kernel<<<1, 1>>>();
    scatter_kernel<<<TT / 256, 256>>>();

    dim3 g1(MTILES, FFDIM / BN, EE);
    moe_gemm_mma<0><<<g1, 128, SMEM_TOTAL>>>(x, W1, nullptr);

    dim3 g2(MTILES, DD / BN, EE);
    moe_gemm_mma<1><<<g2, 128, SMEM_TOTAL>>>(nullptr, W2, out);
}